// round 15
// baseline (speedup 1.0000x reference)
#include <cuda_runtime.h>
#include <cstdint>

// Problem constants (fixed by the reference):
//   encoder_outputs : [B, L, D] f32   = d_in[0]
//   durations       : [B, L]    i32   = d_in[1]
//   frames_positions: [B, T, P] f32   = d_in[2]
//   input_lengths   : [B]       i32   = d_in[3]  (UNUSED by reference)
//   output          : [B, T, D+P] f32
#define BB 16
#define LL 512
#define DD 512
#define TT 4096
#define PP 4

#define DV (DD / 4)          // 128 float4 per encoder row
#define ROW_V (DV + 1)       // 129 float4 per output row (516 floats, 2064 B)
#define RPG 4                // rows per 128-lane group
#define ROWS_PB 16           // rows per block (4 groups * RPG)
#define BLKS_PER_B (TT / ROWS_PB)       // 256 blocks per batch
#define BLK_F4 (ROWS_PB * ROW_V)        // 2064 float4 = 33024 B per block
#define BLK_BYTES (BLK_F4 * 16)

// ---------------------------------------------------------------------------
// Single fused kernel, round-15: bulk-store Phase B.
//  - Phase A: in-block warp-shuffle cumsum of the batch's 512 durations +
//    scatter of token indices for this block's 16-frame window into smem.
//  - Phase B: gather encoder rows (independent LDG.128, R9 structure) into a
//    shared-memory staging image of the block's contiguous 33024-byte output
//    region, then emit it with ONE cp.async.bulk shared->global bulk store.
//    This removes ~1M STG.128 wavefronts from the L1tex path (the top gauge
//    at ~55% across all prior rounds) and hands the write stream to the
//    dedicated bulk-copy engine (full-line streaming writes, no
//    read-allocate, same replay-safe behavior as __stcs).
// ---------------------------------------------------------------------------
__global__ __launch_bounds__(512) void durian_fused_kernel(
    const int*    __restrict__ dur,   // [B, L]
    const float4* __restrict__ enc,   // [B*L, 128] float4
    const float4* __restrict__ fp,    // [B*T] float4
    float4*       __restrict__ out)   // [B*T, 129] float4
{
    __shared__ int s_wsum[16];
    __shared__ int s_idx[ROWS_PB];
    __shared__ __align__(128) float4 s_out[BLK_F4];   // 33024 B staging

    const int tid   = threadIdx.x;
    const int b     = blockIdx.x >> 8;            // / BLKS_PER_B
    const int blk   = blockIdx.x & (BLKS_PER_B - 1);
    const int t0    = blk * ROWS_PB;              // first frame of this block
    const int row0g = b * TT + t0;                // first global output row

    // ---- Phase A: per-batch inclusive cumsum of durations (L=512) --------
    const int lane = tid & 31;
    const int wid  = tid >> 5;                    // 16 warps
    const int d    = dur[b * LL + tid];           // one duration per thread
    int x = d;
    #pragma unroll
    for (int o = 1; o < 32; o <<= 1) {
        int y = __shfl_up_sync(0xffffffffu, x, o);
        if (lane >= o) x += y;
    }
    if (lane == 31) s_wsum[wid] = x;
    if (tid < ROWS_PB) s_idx[tid] = -1;           // init window map
    __syncthreads();
    if (wid == 0) {
        int w = (lane < 16) ? s_wsum[lane] : 0;
        #pragma unroll
        for (int o = 1; o < 16; o <<= 1) {
            int y = __shfl_up_sync(0xffffffffu, w, o);
            if (lane >= o) w += y;
        }
        if (lane < 16) s_wsum[lane] = w;          // inclusive warp prefix
    }
    __syncthreads();

    // Token tid covers frames [end - d, end); end = inclusive cumsum.
    const int prefix = (wid == 0) ? 0 : s_wsum[wid - 1];
    const int end    = prefix + x;
    const int start  = end - d;

    // Scatter into this block's 16-frame window (disjoint ranges, no races)
    int lo = start > t0 ? start : t0;
    int hi = end < t0 + ROWS_PB ? end : t0 + ROWS_PB;
    for (int t = lo; t < hi; t++)
        s_idx[t - t0] = tid;
    __syncthreads();

    // ---- Phase B: gather into smem staging, then ONE bulk store ----------
    const int grp   = tid >> 7;                   // 0..3 group within block
    const int flane = tid & 127;                  // float4 column within row
    const int lrow0 = grp * RPG;                  // local first row of group

    int idx[RPG];
    #pragma unroll
    for (int r = 0; r < RPG; r++)
        idx[r] = s_idx[lrow0 + r];                // LDS broadcast

    // Positions tail value (independent load, overlaps the gathers)
    float4 tail;
    if (flane < RPG)
        tail = fp[row0g + lrow0 + flane];

    const float4* encb = enc + (size_t)b * LL * DV;
    float4 v[RPG];
    #pragma unroll
    for (int r = 0; r < RPG; r++) {
        if (idx[r] >= 0)
            v[r] = encb[(size_t)idx[r] * DV + flane];
        else
            v[r] = make_float4(0.f, 0.f, 0.f, 0.f);
    }

    // Stage rows in smem (warp-conflict-free: consecutive lanes hit
    // consecutive banks at row stride 129 float4)
    #pragma unroll
    for (int r = 0; r < RPG; r++)
        s_out[(lrow0 + r) * ROW_V + flane] = v[r];
    if (flane < RPG)
        s_out[(lrow0 + flane) * ROW_V + DV] = tail;
    __syncthreads();

    // Make generic-proxy STS visible to the async proxy, then bulk-store the
    // whole 33024-byte region (16B-aligned src/dst, size % 16 == 0).
    asm volatile("fence.proxy.async.shared::cta;" ::: "memory");
    if (tid == 0) {
        uint32_t saddr;
        asm("{ .reg .u64 t; cvta.to.shared.u64 t, %1; cvt.u32.u64 %0, t; }"
            : "=r"(saddr) : "l"(s_out));
        const float4* gdst = out + (size_t)row0g * ROW_V;
        asm volatile(
            "cp.async.bulk.global.shared::cta.bulk_group [%0], [%1], %2;"
            :: "l"(gdst), "r"(saddr), "r"((uint32_t)BLK_BYTES)
            : "memory");
        asm volatile("cp.async.bulk.commit_group;" ::: "memory");
        // Keep the block (and its smem) alive until the engine has consumed it
        asm volatile("cp.async.bulk.wait_group 0;" ::: "memory");
    }
}

extern "C" void kernel_launch(void* const* d_in, const int* in_sizes, int n_in,
                              void* d_out, int out_size) {
    const float* enc = (const float*)d_in[0];
    const int*   dur = (const int*)  d_in[1];
    const float* fp  = (const float*)d_in[2];
    // d_in[3] = input_lengths: unused by the reference.
    (void)in_sizes; (void)n_in; (void)out_size;

    durian_fused_kernel<<<BB * BLKS_PER_B, 512>>>(
        dur,
        (const float4*)enc,
        (const float4*)fp,
        (float4*)d_out);
}

// round 16
// speedup vs baseline: 1.0533x; 1.0533x over previous
#include <cuda_runtime.h>

// Problem constants (fixed by the reference):
//   encoder_outputs : [B, L, D] f32   = d_in[0]
//   durations       : [B, L]    i32   = d_in[1]
//   frames_positions: [B, T, P] f32   = d_in[2]
//   input_lengths   : [B]       i32   = d_in[3]  (UNUSED by reference)
//   output          : [B, T, D+P] f32
#define BB 16
#define LL 512
#define DD 512
#define TT 4096
#define PP 4

#define DV (DD / 4)          // 128 float4 per encoder row
#define ROW_V (DV + 1)       // 129 float4 per output row (516 floats, 2064 B)
#define RPG 8                // rows per gather chunk (R9 ILP batch)
#define CHUNKS 4             // Phase-B chunks per group
#define ROWS_PG (RPG * CHUNKS)          // 32 rows per 128-lane group
#define ROWS_PB (4 * ROWS_PG)           // 128 frames per block
#define BLKS_PER_B (TT / ROWS_PB)       // 32 blocks per batch

// ---------------------------------------------------------------------------
// Single fused kernel, round-16: amortized Phase A.
// Each block owns a 128-frame window (4x the R9 window):
//  - Phase A runs ONCE per block (vs 4x in R9's layout): warp-shuffle cumsum
//    of the batch's 512 durations + a single scatter of token indices over
//    the whole 128-frame window.  -> scan/barrier/dur-load overhead / 4.
//  - Phase B is the UNCHANGED R9 champion body (8-deep independent LDG.128
//    gather + __stcs row stores), executed 4x back-to-back with NO barriers
//    between chunks (s_idx is read-only after the single sync), letting the
//    scheduler interleave chunk c+1 loads under chunk c stores.
//  - 512 blocks total = one full wave at 4 blocks/SM (no wave transitions).
// ---------------------------------------------------------------------------
__global__ __launch_bounds__(512) void durian_fused_kernel(
    const int*    __restrict__ dur,   // [B, L]
    const float4* __restrict__ enc,   // [B*L, 128] float4
    const float4* __restrict__ fp,    // [B*T] float4
    float4*       __restrict__ out)   // [B*T, 129] float4
{
    __shared__ int s_wsum[16];
    __shared__ int s_idx[ROWS_PB];    // 128-frame window map

    const int tid   = threadIdx.x;
    const int b     = blockIdx.x >> 5;            // / BLKS_PER_B
    const int blk   = blockIdx.x & (BLKS_PER_B - 1);
    const int t0    = blk * ROWS_PB;              // first frame of this block
    const int row0g = b * TT + t0;                // first global output row

    // ---- Phase A (once per 128 frames): cumsum + window scatter ----------
    const int lane = tid & 31;
    const int wid  = tid >> 5;                    // 16 warps
    const int d    = dur[b * LL + tid];           // one duration per thread
    int x = d;
    #pragma unroll
    for (int o = 1; o < 32; o <<= 1) {
        int y = __shfl_up_sync(0xffffffffu, x, o);
        if (lane >= o) x += y;
    }
    if (lane == 31) s_wsum[wid] = x;
    if (tid < ROWS_PB) s_idx[tid] = -1;           // init window map
    __syncthreads();
    if (wid == 0) {
        int w = (lane < 16) ? s_wsum[lane] : 0;
        #pragma unroll
        for (int o = 1; o < 16; o <<= 1) {
            int y = __shfl_up_sync(0xffffffffu, w, o);
            if (lane >= o) w += y;
        }
        if (lane < 16) s_wsum[lane] = w;          // inclusive warp prefix
    }
    __syncthreads();

    // Token tid covers frames [end - d, end); end = inclusive cumsum.
    const int prefix = (wid == 0) ? 0 : s_wsum[wid - 1];
    const int end    = prefix + x;
    const int start  = end - d;

    // Scatter into this block's 128-frame window (disjoint ranges, no races)
    int lo = start > t0 ? start : t0;
    int hi = end < t0 + ROWS_PB ? end : t0 + ROWS_PB;
    for (int t = lo; t < hi; t++)
        s_idx[t - t0] = tid;
    __syncthreads();

    // ---- Phase B: 4 chunks of the R9 body, no barriers between -----------
    const int grp   = tid >> 7;                   // 0..3 group within block
    const int flane = tid & 127;                  // float4 column within row
    const float4* encb = enc + (size_t)b * LL * DV;

    #pragma unroll
    for (int c = 0; c < CHUNKS; c++) {
        const int lrow0 = grp * ROWS_PG + c * RPG;   // local first row
        const int rowg  = row0g + lrow0;             // global first row

        int idx[RPG];
        #pragma unroll
        for (int r = 0; r < RPG; r++)
            idx[r] = s_idx[lrow0 + r];               // LDS broadcast

        // Positions tail value (independent load, overlaps the gathers)
        float4 tail;
        if (flane < RPG)
            tail = fp[rowg + flane];

        float4 v[RPG];
        #pragma unroll
        for (int r = 0; r < RPG; r++) {
            if (idx[r] >= 0)
                v[r] = encb[(size_t)idx[r] * DV + flane];
            else
                v[r] = make_float4(0.f, 0.f, 0.f, 0.f);
        }

        // Streaming row stores (evict-first: replay-safe, R10 showed default
        // policy costs +5us of L2 churn across graph replays)
        #pragma unroll
        for (int r = 0; r < RPG; r++)
            __stcs(&out[(size_t)(rowg + r) * ROW_V + flane], v[r]);

        if (flane < RPG)
            __stcs(&out[(size_t)(rowg + flane) * ROW_V + DV], tail);
    }
}

extern "C" void kernel_launch(void* const* d_in, const int* in_sizes, int n_in,
                              void* d_out, int out_size) {
    const float* enc = (const float*)d_in[0];
    const int*   dur = (const int*)  d_in[1];
    const float* fp  = (const float*)d_in[2];
    // d_in[3] = input_lengths: unused by the reference.
    (void)in_sizes; (void)n_in; (void)out_size;

    durian_fused_kernel<<<BB * BLKS_PER_B, 512>>>(
        dur,
        (const float4*)enc,
        (const float4*)fp,
        (float4*)d_out);
}

// round 17
// speedup vs baseline: 1.2309x; 1.1686x over previous
#include <cuda_runtime.h>

// Problem constants (fixed by the reference):
//   encoder_outputs : [B, L, D] f32   = d_in[0]
//   durations       : [B, L]    i32   = d_in[1]
//   frames_positions: [B, T, P] f32   = d_in[2]
//   input_lengths   : [B]       i32   = d_in[3]  (UNUSED by reference)
//   output          : [B, T, D+P] f32
#define BB 16
#define LL 512
#define DD 512
#define TT 4096
#define PP 4

#define DV (DD / 4)          // 128 float4 per encoder row
#define ROW_V (DV + 1)       // 129 float4 per output row (516 floats, 2064 B)
#define RPG 8                // rows per 128-lane group (ILP batch)
#define ROWS_PB 32           // rows per block (4 groups * RPG)
#define BLKS_PER_B (TT / ROWS_PB)   // 128 blocks per batch

// ---------------------------------------------------------------------------
// FINAL kernel = round-9 champion, reverted verbatim (25.06us measured).
// Certified against 7 structural alternatives (forced-MLP fence, default
// stores, linear-aligned stores, 256-bit v8 stores, gather dedup, TMA bulk
// store, amortized 128-frame scan) — all measured equal or worse. The kernel
// sits at the DRAM write wall: 135.3 MB of output per replay at ~5.4 TB/s of
// pure writes (~68% of combined-spec HBM), which is the practical ceiling.
//
// Structure:
//  Phase A: in-block warp-shuffle inclusive cumsum of the batch's 512
//           durations + scatter of covering token indices for this block's
//           32-frame window into smem (searchsorted side="right" semantics;
//           -1 marks frames past the total -> zero rows).
//  Phase B: each 128-lane group owns 8 consecutive output rows: 8 independent
//           LDG.128 encoder gathers (MLP=8, consecutive rows mostly L1/L2
//           hits), 8 __stcs streaming row stores (evict-first keeps L2 stable
//           across graph replays; default policy measured +5us churn), and a
//           per-lane positions tail store.
// ---------------------------------------------------------------------------
__global__ __launch_bounds__(512) void durian_fused_kernel(
    const int*    __restrict__ dur,   // [B, L]
    const float4* __restrict__ enc,   // [B*L, 128] float4
    const float4* __restrict__ fp,    // [B*T] float4
    float4*       __restrict__ out)   // [B*T, 129] float4
{
    __shared__ int s_wsum[16];
    __shared__ int s_idx[ROWS_PB];

    const int tid   = threadIdx.x;
    const int b     = blockIdx.x >> 7;            // / BLKS_PER_B
    const int blk   = blockIdx.x & (BLKS_PER_B - 1);
    const int t0    = blk * ROWS_PB;              // first frame of this block
    const int row0g = b * TT + t0;                // first global output row

    // ---- Phase A: per-batch inclusive cumsum of durations (L=512) --------
    const int lane = tid & 31;
    const int wid  = tid >> 5;                    // 16 warps
    const int d    = dur[b * LL + tid];           // one duration per thread
    int x = d;
    #pragma unroll
    for (int o = 1; o < 32; o <<= 1) {
        int y = __shfl_up_sync(0xffffffffu, x, o);
        if (lane >= o) x += y;
    }
    if (lane == 31) s_wsum[wid] = x;
    if (tid < ROWS_PB) s_idx[tid] = -1;           // init window map
    __syncthreads();
    if (wid == 0) {
        int w = (lane < 16) ? s_wsum[lane] : 0;
        #pragma unroll
        for (int o = 1; o < 16; o <<= 1) {
            int y = __shfl_up_sync(0xffffffffu, w, o);
            if (lane >= o) w += y;
        }
        if (lane < 16) s_wsum[lane] = w;          // inclusive warp prefix
    }
    __syncthreads();

    // Token tid covers frames [end - d, end); end = inclusive cumsum.
    const int prefix = (wid == 0) ? 0 : s_wsum[wid - 1];
    const int end    = prefix + x;
    const int start  = end - d;

    // Scatter into this block's 32-frame window (disjoint ranges, no races)
    int lo = start > t0 ? start : t0;
    int hi = end < t0 + ROWS_PB ? end : t0 + ROWS_PB;
    for (int t = lo; t < hi; t++)
        s_idx[t - t0] = tid;
    __syncthreads();

    // ---- Phase B: expansion + concat ------------------------------------
    const int grp   = tid >> 7;                   // 0..3 group within block
    const int flane = tid & 127;                  // float4 column within row
    const int lrow0 = grp * RPG;                  // local first row of group
    const int rowg  = row0g + lrow0;              // first global row of group

    int idx[RPG];
    #pragma unroll
    for (int r = 0; r < RPG; r++)
        idx[r] = s_idx[lrow0 + r];                // LDS broadcast

    // Positions tail value (independent load, overlaps the gathers)
    float4 tail;
    if (flane < RPG)
        tail = fp[rowg + flane];

    const float4* encb = enc + (size_t)b * LL * DV;
    float4 v[RPG];
    #pragma unroll
    for (int r = 0; r < RPG; r++) {
        if (idx[r] >= 0)
            v[r] = encb[(size_t)idx[r] * DV + flane];
        else
            v[r] = make_float4(0.f, 0.f, 0.f, 0.f);
    }

    // 8 independent streaming stores (write-once output, evict-first)
    #pragma unroll
    for (int r = 0; r < RPG; r++)
        __stcs(&out[(size_t)(rowg + r) * ROW_V + flane], v[r]);

    // Positions tail: lanes 0..7 of each group handle one row each
    if (flane < RPG)
        __stcs(&out[(size_t)(rowg + flane) * ROW_V + DV], tail);
}

extern "C" void kernel_launch(void* const* d_in, const int* in_sizes, int n_in,
                              void* d_out, int out_size) {
    const float* enc = (const float*)d_in[0];
    const int*   dur = (const int*)  d_in[1];
    const float* fp  = (const float*)d_in[2];
    // d_in[3] = input_lengths: unused by the reference.
    (void)in_sizes; (void)n_in; (void)out_size;

    durian_fused_kernel<<<BB * BLKS_PER_B, 512>>>(
        dur,
        (const float4*)enc,
        (const float4*)fp,
        (float4*)d_out);
}